// round 14
// baseline (speedup 1.0000x reference)
#include <cuda_runtime.h>
#include <cuda_bf16.h>
#include <math.h>

#define N_   8192
#define D_   2048
#define P_   512
#define NB_  16          // k0 partition blocks (512 samples each)
#define EPSF 1e-12f
#define S_   4           // k1 LDGSTS ring depth (4 x 8KB static smem)

// ---------------- scratch (device globals; no allocation allowed) ----------
__device__ int   g_count[P_];
__device__ int   g_offset[P_];
__device__ int   g_members[N_];
__device__ int   g_pc[NB_][P_];              // per-partition class histograms
__device__ __nv_bfloat16 g_cbf[3][P_][D_];   // unit centers, bf16
__device__ float g_part[3][4][P_][P_];       // split-K partial dot planes (12MB)
__device__ float g_rowloss[3 * P_];
__device__ float g_sumnorm;                  // sum ||s_c|| over all (m, c)

// ---------------- helpers --------------------------------------------------
__device__ __forceinline__ float warpSum(float v) {
#pragma unroll
    for (int o = 16; o; o >>= 1) v += __shfl_xor_sync(0xffffffffu, v, o);
    return v;
}
__device__ __forceinline__ unsigned bfpack(float lo, float hi) {
    unsigned a = (unsigned)__bfloat16_as_ushort(__float2bfloat16_rn(lo));
    unsigned b = (unsigned)__bfloat16_as_ushort(__float2bfloat16_rn(hi));
    return a | (b << 16);
}
__device__ __forceinline__ float dot8(const float4& x, const float4& y) {
    return x.x * x.x + x.y * x.y + x.z * x.z + x.w * x.w
         + y.x * y.x + y.y * y.y + y.z * y.z + y.w * y.w;
}
__device__ __forceinline__ void cpa16(void* dst, const void* src) {
    unsigned d = (unsigned)__cvta_generic_to_shared(dst);
    asm volatile("cp.async.cg.shared.global [%0], [%1], 16;\n" :: "r"(d), "l"(src));
}
__device__ __forceinline__ void cpa_commit() {
    asm volatile("cp.async.commit_group;\n" ::: "memory");
}
template <int Npend>
__device__ __forceinline__ void cpa_wait() {
    asm volatile("cp.async.wait_group %0;\n" :: "n"(Npend) : "memory");
}

// ---------------- kernel 0a: per-partition histogram + zero sumnorm --------
__global__ void __launch_bounds__(512) k0a_hist(const int* __restrict__ label) {
    __shared__ int h[P_];
    int t = threadIdx.x, b = blockIdx.x;
    h[t] = 0;
    __syncthreads();
    int l = __ldg(&label[b * 512 + t]);
    atomicAdd(&h[l], 1);
    __syncthreads();
    g_pc[b][t] = h[t];
    if (b == 0 && t == 0) g_sumnorm = 0.f;
}

// ---------------- kernel 0b: redundant scan + parallel fill (grid NB_) -----
__global__ void __launch_bounds__(512) k0b_fill(const int* __restrict__ label) {
    __shared__ int cur[P_];
    __shared__ int ws[16];
    int t = threadIdx.x, b = blockIdx.x, lane = t & 31, w = t >> 5;

    int pref = 0, tot = 0;
#pragma unroll
    for (int bb = 0; bb < NB_; bb++) {
        int v = g_pc[bb][t];
        if (bb < b) pref += v;
        tot += v;
    }
    int inc = tot;
#pragma unroll
    for (int o = 1; o < 32; o <<= 1) {
        int v = __shfl_up_sync(0xffffffffu, inc, o);
        if (lane >= o) inc += v;
    }
    if (lane == 31) ws[w] = inc;
    __syncthreads();
    if (t < 32) {
        int v = (t < 16) ? ws[t] : 0;
        int s = v;
#pragma unroll
        for (int o = 1; o < 32; o <<= 1) {
            int u = __shfl_up_sync(0xffffffffu, s, o);
            if (lane >= o) s += u;
        }
        if (t < 16) ws[t] = s - v;
    }
    __syncthreads();
    int exc = ws[w] + inc - tot;          // exclusive class prefix
    if (b == 0) { g_count[t] = tot; g_offset[t] = exc; }
    cur[t] = exc + pref;                  // this partition's write base
    __syncthreads();
    int i = b * 512 + t;
    int c = __ldg(&label[i]);
    int pos = atomicAdd(&cur[c], 1);
    g_members[pos] = i;
}

// ---------------- kernel 1: centers, LDGSTS ring + ROW PAIRING -------------
// grid (P_, nm), block 256. 4-stage ring; two rows per barrier (ILP'd shfl
// chains, half the barriers). moff selects modality window.
__global__ void __launch_bounds__(256) k1_centers(const float* __restrict__ f0,
                                                  const float* __restrict__ f1,
                                                  const float* __restrict__ f2,
                                                  int moff) {
    int c = blockIdx.x, m = blockIdx.y + moff;
    const float* f = (m == 0) ? f0 : ((m == 1) ? f1 : f2);
    int off = g_offset[c];
    int K   = g_count[c];
    int t   = threadIdx.x, w = t >> 5, lane = t & 31;

    __shared__ __align__(16) float stg[S_][D_];   // 32 KB ring
    __shared__ float wred[2][2][8];               // [pair parity][row][warp]

#pragma unroll
    for (int s = 0; s < S_; s++) {
        if (s < K) {
            int row = __ldg(&g_members[off + s]);
            const float* src = f + (size_t)row * D_;
            cpa16(&stg[s][t * 4], src + t * 4);
            cpa16(&stg[s][1024 + t * 4], src + 1024 + t * 4);
        }
        cpa_commit();
    }

    float a0 = 0.f, a1 = 0.f, a2 = 0.f, a3 = 0.f;
    float a4 = 0.f, a5 = 0.f, a6 = 0.f, a7 = 0.f;

    int k = 0;
    for (; k + 1 < K; k += 2) {
        cpa_wait<S_ - 2>();          // stages k and k+1 landed
        int sb0 = k & (S_ - 1), sb1 = (k + 1) & (S_ - 1);
        float4 x0 = *(const float4*)&stg[sb0][t * 4];
        float4 y0 = *(const float4*)&stg[sb0][1024 + t * 4];
        float4 x1 = *(const float4*)&stg[sb1][t * 4];
        float4 y1 = *(const float4*)&stg[sb1][1024 + t * 4];
        // refill both freed stages (own region only: no cross-thread hazard);
        // always commit two groups to keep wait<2> accounting uniform.
        int kn0 = k + S_, kn1 = k + 1 + S_;
        if (kn0 < K) {
            int row = __ldg(&g_members[off + kn0]);
            const float* src = f + (size_t)row * D_;
            cpa16(&stg[sb0][t * 4], src + t * 4);
            cpa16(&stg[sb0][1024 + t * 4], src + 1024 + t * 4);
        }
        cpa_commit();
        if (kn1 < K) {
            int row = __ldg(&g_members[off + kn1]);
            const float* src = f + (size_t)row * D_;
            cpa16(&stg[sb1][t * 4], src + t * 4);
            cpa16(&stg[sb1][1024 + t * 4], src + 1024 + t * 4);
        }
        cpa_commit();

        float ss0 = dot8(x0, y0), ss1 = dot8(x1, y1);
#pragma unroll
        for (int o = 16; o; o >>= 1) {     // two interleaved shfl chains (ILP)
            ss0 += __shfl_xor_sync(0xffffffffu, ss0, o);
            ss1 += __shfl_xor_sync(0xffffffffu, ss1, o);
        }
        int pb = (k >> 1) & 1;
        if (lane == 0) { wred[pb][0][w] = ss0; wred[pb][1][w] = ss1; }
        __syncthreads();                   // ONE barrier per two rows
        float t0 = wred[pb][0][0] + wred[pb][0][1] + wred[pb][0][2] + wred[pb][0][3]
                 + wred[pb][0][4] + wred[pb][0][5] + wred[pb][0][6] + wred[pb][0][7];
        float t1 = wred[pb][1][0] + wred[pb][1][1] + wred[pb][1][2] + wred[pb][1][3]
                 + wred[pb][1][4] + wred[pb][1][5] + wred[pb][1][6] + wred[pb][1][7];
        float i0 = rsqrtf(fmaxf(t0, 1e-24f));
        float i1 = rsqrtf(fmaxf(t1, 1e-24f));
        a0 += x0.x * i0 + x1.x * i1; a1 += x0.y * i0 + x1.y * i1;
        a2 += x0.z * i0 + x1.z * i1; a3 += x0.w * i0 + x1.w * i1;
        a4 += y0.x * i0 + y1.x * i1; a5 += y0.y * i0 + y1.y * i1;
        a6 += y0.z * i0 + y1.z * i1; a7 += y0.w * i0 + y1.w * i1;
    }
    if (k < K) {                     // odd tail row
        cpa_wait<0>();
        int sb = k & (S_ - 1);
        float4 x = *(const float4*)&stg[sb][t * 4];
        float4 y = *(const float4*)&stg[sb][1024 + t * 4];
        float ss = warpSum(dot8(x, y));
        if (lane == 0) wred[0][0][w] = ss;
        __syncthreads();
        float tt = wred[0][0][0] + wred[0][0][1] + wred[0][0][2] + wred[0][0][3]
                 + wred[0][0][4] + wred[0][0][5] + wred[0][0][6] + wred[0][0][7];
        float iv = rsqrtf(fmaxf(tt, 1e-24f));
        a0 += x.x * iv; a1 += x.y * iv; a2 += x.z * iv; a3 += x.w * iv;
        a4 += y.x * iv; a5 += y.y * iv; a6 += y.z * iv; a7 += y.w * iv;
    }

    float ss2 = a0 * a0 + a1 * a1 + a2 * a2 + a3 * a3
              + a4 * a4 + a5 * a5 + a6 * a6 + a7 * a7;
    ss2 = warpSum(ss2);
    __syncthreads();
    if (lane == 0) wred[0][0][w] = ss2;
    __syncthreads();
    float tot2 = wred[0][0][0] + wred[0][0][1] + wred[0][0][2] + wred[0][0][3]
               + wred[0][0][4] + wred[0][0][5] + wred[0][0][6] + wred[0][0][7];
    float nrm  = sqrtf(tot2);
    float inv2 = 1.f / fmaxf(nrm, EPSF);

    __nv_bfloat16* cb = &g_cbf[m][c][0];
    uint2 u0, u1;
    u0.x = bfpack(a0 * inv2, a1 * inv2); u0.y = bfpack(a2 * inv2, a3 * inv2);
    u1.x = bfpack(a4 * inv2, a5 * inv2); u1.y = bfpack(a6 * inv2, a7 * inv2);
    *(uint2*)(cb + 4 * t)         = u0;
    *(uint2*)(cb + 4 * (t + 256)) = u1;
    if (t == 0) atomicAdd(&g_sumnorm, nrm);
}

// ---------------- kernel 2: split-K bf16 mma GEMM, 2-stage cp.async --------
// grid (8, 8, 4*np): z = (p-p0)*4 + ks. 64x64 tile over K=512 (8 chunks).
#define KC_ 64
#define NC_ (512 / KC_)
__device__ __forceinline__ unsigned sw_off(int row, int g) {
    return (unsigned)(row * 128 + ((g ^ (row & 7)) << 4));
}

__global__ void __launch_bounds__(128) k2_gemm(int p0) {
    __shared__ __align__(16) unsigned char As[2][64 * 128];
    __shared__ __align__(16) unsigned char Bs[2][64 * 128];

    int z  = blockIdx.z;
    int p  = p0 + (z >> 2), ks = z & 3;
    int pa = (p == 2) ? 1 : 0;
    int pb = (p == 0) ? 1 : 2;
    const __nv_bfloat16* A = &g_cbf[pa][0][0];
    const __nv_bfloat16* B = &g_cbf[pb][0][0];

    int t = threadIdx.x, lane = t & 31, warp = t >> 5;
    int wr = warp >> 1, wc = warp & 1;
    int brow = blockIdx.y * 64, bcol = blockIdx.x * 64;
    int k0 = ks * 512;

    float acc[2][4][4];
#pragma unroll
    for (int mt = 0; mt < 2; mt++)
#pragma unroll
        for (int nt = 0; nt < 4; nt++)
#pragma unroll
            for (int e = 0; e < 4; e++) acc[mt][nt][e] = 0.f;

    int rsel = lane & 15, gsel = lane >> 4;

#pragma unroll
    for (int j = 0; j < 4; j++) {
        int i = t + j * 128, row = i >> 3, g = i & 7;
        cpa16(&As[0][sw_off(row, g)], A + (size_t)(brow + row) * D_ + k0 + g * 8);
        cpa16(&Bs[0][sw_off(row, g)], B + (size_t)(bcol + row) * D_ + k0 + g * 8);
    }
    cpa_commit();

    for (int lc = 0; lc < NC_; lc++) {
        int st = lc & 1;
        if (lc + 1 < NC_) {
            int co = k0 + (lc + 1) * KC_;
            int ns = st ^ 1;
#pragma unroll
            for (int j = 0; j < 4; j++) {
                int i = t + j * 128, row = i >> 3, g = i & 7;
                cpa16(&As[ns][sw_off(row, g)], A + (size_t)(brow + row) * D_ + co + g * 8);
                cpa16(&Bs[ns][sw_off(row, g)], B + (size_t)(bcol + row) * D_ + co + g * 8);
            }
            cpa_commit();
            cpa_wait<1>();
        } else {
            cpa_wait<0>();
        }
        __syncthreads();

        unsigned ab = (unsigned)__cvta_generic_to_shared(&As[st][0]);
        unsigned bb = (unsigned)__cvta_generic_to_shared(&Bs[st][0]);
#pragma unroll
        for (int kh = 0; kh < 4; kh++) {
            unsigned af[2][4], bfr[2][4];
#pragma unroll
            for (int mt = 0; mt < 2; mt++) {
                unsigned ad = ab + sw_off(wr * 32 + mt * 16 + rsel, kh * 2 + gsel);
                asm volatile("ldmatrix.sync.aligned.m8n8.x4.shared.b16 {%0,%1,%2,%3}, [%4];"
                             : "=r"(af[mt][0]), "=r"(af[mt][1]), "=r"(af[mt][2]), "=r"(af[mt][3])
                             : "r"(ad));
            }
#pragma unroll
            for (int np = 0; np < 2; np++) {
                unsigned bd = bb + sw_off(wc * 32 + np * 16 + rsel, kh * 2 + gsel);
                asm volatile("ldmatrix.sync.aligned.m8n8.x4.shared.b16 {%0,%1,%2,%3}, [%4];"
                             : "=r"(bfr[np][0]), "=r"(bfr[np][1]), "=r"(bfr[np][2]), "=r"(bfr[np][3])
                             : "r"(bd));
            }
#pragma unroll
            for (int mt = 0; mt < 2; mt++)
#pragma unroll
                for (int nt = 0; nt < 4; nt++) {
                    int np = nt >> 1, s = nt & 1;
                    asm volatile(
                        "mma.sync.aligned.m16n8k16.row.col.f32.bf16.bf16.f32 "
                        "{%0,%1,%2,%3},{%4,%5,%6,%7},{%8,%9},{%0,%1,%2,%3};"
                        : "+f"(acc[mt][nt][0]), "+f"(acc[mt][nt][1]),
                          "+f"(acc[mt][nt][2]), "+f"(acc[mt][nt][3])
                        : "r"(af[mt][0]), "r"(af[mt][1]), "r"(af[mt][2]), "r"(af[mt][3]),
                          "r"(bfr[np][0 + s]), "r"(bfr[np][2 + s]));
                }
        }
        __syncthreads();
    }

    float* C = &g_part[p][ks][0][0];
#pragma unroll
    for (int mt = 0; mt < 2; mt++)
#pragma unroll
        for (int nt = 0; nt < 4; nt++) {
            int row = brow + wr * 32 + mt * 16 + (lane >> 2);
            int col = bcol + wc * 32 + nt * 8 + (lane & 3) * 2;
            *(float2*)(C + (size_t)row * P_ + col)       = make_float2(acc[mt][nt][0], acc[mt][nt][1]);
            *(float2*)(C + (size_t)(row + 8) * P_ + col) = make_float2(acc[mt][nt][2], acc[mt][nt][3]);
        }
}

// ---------------- kernel 3a: combine splits + exp-sum + diag, warp/row -----
// grid 192, block 256 (8 warps). Logits bounded (|2*dot|<=2): no max shift.
__global__ void __launch_bounds__(256) k3_row() {
    int warp = threadIdx.x >> 5, lane = threadIdx.x & 31;
    int gid = blockIdx.x * 8 + warp;          // 0 .. 1535
    int p = gid >> 9, i = gid & (P_ - 1);
    const float* b0 = &g_part[p][0][i][0];    // plane stride P_*P_

    float es = 0.f, dg = 0.f;
#pragma unroll
    for (int j = 0; j < 4; j++) {
        int c0 = lane * 4 + j * 128;
        float4 v0 = *(const float4*)(b0 + c0);
        float4 v1 = *(const float4*)(b0 + P_ * P_ + c0);
        float4 v2 = *(const float4*)(b0 + 2 * P_ * P_ + c0);
        float4 v3 = *(const float4*)(b0 + 3 * P_ * P_ + c0);
        float sx = v0.x + v1.x + v2.x + v3.x;
        float sy = v0.y + v1.y + v2.y + v3.y;
        float sz = v0.z + v1.z + v2.z + v3.z;
        float sw = v0.w + v1.w + v2.w + v3.w;
        es += __expf(2.f * sx) + __expf(2.f * sy)
            + __expf(2.f * sz) + __expf(2.f * sw);
        if (i == c0)     dg += sx;
        if (i == c0 + 1) dg += sy;
        if (i == c0 + 2) dg += sz;
        if (i == c0 + 3) dg += sw;
    }
    es = warpSum(es);
    dg = warpSum(dg);
    if (lane == 0) g_rowloss[gid] = __logf(es) - 2.f * dg;
}

// ---------------- kernel 3b: final scalar ----------------------------------
__global__ void __launch_bounds__(512) k3_final(float* __restrict__ out) {
    int t = threadIdx.x;  // 512 threads
    float rl = g_rowloss[t] + g_rowloss[t + 512] + g_rowloss[t + 1024];
    __shared__ float w1[16];
    rl = warpSum(rl);
    if ((t & 31) == 0) w1[t >> 5] = rl;
    __syncthreads();
    if (t == 0) {
        float R = 0.f;
        for (int i = 0; i < 16; i++) R += w1[i];
        // loss_intra = 6 - (2/N)*sum||s||;  loss_inter = (sum rowloss)/P
        out[0] = 6.f - g_sumnorm / 4096.f + R / 512.f;
    }
}

// ---------------- launch: forked-stream graph ------------------------------
// main stream:  k0a -> k0b -> k1(v,a) -[ev1]-> k1(r) -[ev2]  ... -> k3_row -> k3_final
// side stream:  wait ev1 -> k2(v.a)  (overlaps k1(r)) -> wait ev2 -> k2(v.r, a.r) -[ev3]
extern "C" void kernel_launch(void* const* d_in, const int* in_sizes, int n_in,
                              void* d_out, int out_size) {
    const float* fv    = (const float*)d_in[0];
    const float* fa    = (const float*)d_in[1];
    const float* fr    = (const float*)d_in[2];
    const int*   label = (const int*)d_in[3];
    (void)in_sizes; (void)n_in; (void)out_size;

    static bool        s_init = false;
    static cudaStream_t s2;
    static cudaEvent_t  ev1, ev2, ev3;
    if (!s_init) {   // host-side objects only; created on the (non-captured) first call
        cudaStreamCreateWithFlags(&s2, cudaStreamNonBlocking);
        cudaEventCreateWithFlags(&ev1, cudaEventDisableTiming);
        cudaEventCreateWithFlags(&ev2, cudaEventDisableTiming);
        cudaEventCreateWithFlags(&ev3, cudaEventDisableTiming);
        s_init = true;
    }

    k0a_hist<<<NB_, 512>>>(label);
    k0b_fill<<<NB_, 512>>>(label);
    k1_centers<<<dim3(P_, 2), 256>>>(fv, fa, fr, 0);   // modalities v, a
    cudaEventRecord(ev1, 0);
    k1_centers<<<dim3(P_, 1), 256>>>(fv, fa, fr, 2);   // modality r
    cudaEventRecord(ev2, 0);

    cudaStreamWaitEvent(s2, ev1, 0);
    k2_gemm<<<dim3(8, 8, 4), 128, 0, s2>>>(0);         // p=0 (v.a) || k1(r)
    cudaStreamWaitEvent(s2, ev2, 0);
    k2_gemm<<<dim3(8, 8, 8), 128, 0, s2>>>(1);         // p=1,2 (v.r, a.r)
    cudaEventRecord(ev3, s2);

    cudaStreamWaitEvent(0, ev3, 0);
    k3_row<<<192, 256>>>();
    k3_final<<<1, 512>>>((float*)d_out);
}

// round 15
// speedup vs baseline: 1.2577x; 1.2577x over previous
#include <cuda_runtime.h>
#include <cuda_bf16.h>
#include <math.h>

#define N_   8192
#define D_   2048
#define P_   512
#define NB_  16          // k0 partition blocks (512 samples each)
#define EPSF 1e-12f
#define S_   4           // k1 LDGSTS ring depth (4 x 8KB static smem)

// ---------------- scratch (device globals; no allocation allowed) ----------
__device__ int   g_count[P_];
__device__ int   g_offset[P_];
__device__ int   g_members[N_];
__device__ int   g_pc[NB_][P_];              // per-partition class histograms
__device__ __nv_bfloat16 g_cbf[3][P_][D_];   // unit centers, bf16
__device__ float g_part[3][4][P_][P_];       // split-K partial dot planes (12MB)
__device__ float g_rowloss[3 * P_];
__device__ float g_sumnorm;                  // sum ||s_c|| over all (m, c)

// ---------------- helpers --------------------------------------------------
__device__ __forceinline__ float warpSum(float v) {
#pragma unroll
    for (int o = 16; o; o >>= 1) v += __shfl_xor_sync(0xffffffffu, v, o);
    return v;
}
__device__ __forceinline__ unsigned bfpack(float lo, float hi) {
    unsigned a = (unsigned)__bfloat16_as_ushort(__float2bfloat16_rn(lo));
    unsigned b = (unsigned)__bfloat16_as_ushort(__float2bfloat16_rn(hi));
    return a | (b << 16);
}
__device__ __forceinline__ float dot8(const float4& x, const float4& y) {
    return x.x * x.x + x.y * x.y + x.z * x.z + x.w * x.w
         + y.x * y.x + y.y * y.y + y.z * y.z + y.w * y.w;
}
__device__ __forceinline__ void cpa16(void* dst, const void* src) {
    unsigned d = (unsigned)__cvta_generic_to_shared(dst);
    asm volatile("cp.async.cg.shared.global [%0], [%1], 16;\n" :: "r"(d), "l"(src));
}
__device__ __forceinline__ void cpa_commit() {
    asm volatile("cp.async.commit_group;\n" ::: "memory");
}
template <int Npend>
__device__ __forceinline__ void cpa_wait() {
    asm volatile("cp.async.wait_group %0;\n" :: "n"(Npend) : "memory");
}

// ---------------- kernel 0a: per-partition histogram + zero sumnorm --------
__global__ void __launch_bounds__(512) k0a_hist(const int* __restrict__ label) {
    __shared__ int h[P_];
    int t = threadIdx.x, b = blockIdx.x;
    h[t] = 0;
    __syncthreads();
    int l = __ldg(&label[b * 512 + t]);
    atomicAdd(&h[l], 1);
    __syncthreads();
    g_pc[b][t] = h[t];
    if (b == 0 && t == 0) g_sumnorm = 0.f;
}

// ---------------- kernel 0b: redundant scan + parallel fill (grid NB_) -----
__global__ void __launch_bounds__(512) k0b_fill(const int* __restrict__ label) {
    __shared__ int cur[P_];
    __shared__ int ws[16];
    int t = threadIdx.x, b = blockIdx.x, lane = t & 31, w = t >> 5;

    int pref = 0, tot = 0;
#pragma unroll
    for (int bb = 0; bb < NB_; bb++) {
        int v = g_pc[bb][t];
        if (bb < b) pref += v;
        tot += v;
    }
    int inc = tot;
#pragma unroll
    for (int o = 1; o < 32; o <<= 1) {
        int v = __shfl_up_sync(0xffffffffu, inc, o);
        if (lane >= o) inc += v;
    }
    if (lane == 31) ws[w] = inc;
    __syncthreads();
    if (t < 32) {
        int v = (t < 16) ? ws[t] : 0;
        int s = v;
#pragma unroll
        for (int o = 1; o < 32; o <<= 1) {
            int u = __shfl_up_sync(0xffffffffu, s, o);
            if (lane >= o) s += u;
        }
        if (t < 16) ws[t] = s - v;
    }
    __syncthreads();
    int exc = ws[w] + inc - tot;          // exclusive class prefix
    if (b == 0) { g_count[t] = tot; g_offset[t] = exc; }
    cur[t] = exc + pref;                  // this partition's write base
    __syncthreads();
    int i = b * 512 + t;
    int c = __ldg(&label[i]);
    int pos = atomicAdd(&cur[c], 1);
    g_members[pos] = i;
}

// ---------------- kernel 1: centers, LDGSTS ring + row pairing -------------
// grid (P_, 3), block 256. 4-stage ring; two rows per barrier (ILP'd shfl
// chains, half the barriers).
__global__ void __launch_bounds__(256) k1_centers(const float* __restrict__ f0,
                                                  const float* __restrict__ f1,
                                                  const float* __restrict__ f2) {
    int c = blockIdx.x, m = blockIdx.y;
    const float* f = (m == 0) ? f0 : ((m == 1) ? f1 : f2);
    int off = g_offset[c];
    int K   = g_count[c];
    int t   = threadIdx.x, w = t >> 5, lane = t & 31;

    __shared__ __align__(16) float stg[S_][D_];   // 32 KB ring
    __shared__ float wred[2][2][8];               // [pair parity][row][warp]

#pragma unroll
    for (int s = 0; s < S_; s++) {
        if (s < K) {
            int row = __ldg(&g_members[off + s]);
            const float* src = f + (size_t)row * D_;
            cpa16(&stg[s][t * 4], src + t * 4);
            cpa16(&stg[s][1024 + t * 4], src + 1024 + t * 4);
        }
        cpa_commit();
    }

    float a0 = 0.f, a1 = 0.f, a2 = 0.f, a3 = 0.f;
    float a4 = 0.f, a5 = 0.f, a6 = 0.f, a7 = 0.f;

    int k = 0;
    for (; k + 1 < K; k += 2) {
        cpa_wait<S_ - 2>();          // stages k and k+1 landed
        int sb0 = k & (S_ - 1), sb1 = (k + 1) & (S_ - 1);
        float4 x0 = *(const float4*)&stg[sb0][t * 4];
        float4 y0 = *(const float4*)&stg[sb0][1024 + t * 4];
        float4 x1 = *(const float4*)&stg[sb1][t * 4];
        float4 y1 = *(const float4*)&stg[sb1][1024 + t * 4];
        // refill both freed stages (own region only: no cross-thread hazard);
        // always commit two groups to keep wait accounting uniform.
        int kn0 = k + S_, kn1 = k + 1 + S_;
        if (kn0 < K) {
            int row = __ldg(&g_members[off + kn0]);
            const float* src = f + (size_t)row * D_;
            cpa16(&stg[sb0][t * 4], src + t * 4);
            cpa16(&stg[sb0][1024 + t * 4], src + 1024 + t * 4);
        }
        cpa_commit();
        if (kn1 < K) {
            int row = __ldg(&g_members[off + kn1]);
            const float* src = f + (size_t)row * D_;
            cpa16(&stg[sb1][t * 4], src + t * 4);
            cpa16(&stg[sb1][1024 + t * 4], src + 1024 + t * 4);
        }
        cpa_commit();

        float ss0 = dot8(x0, y0), ss1 = dot8(x1, y1);
#pragma unroll
        for (int o = 16; o; o >>= 1) {     // two interleaved shfl chains (ILP)
            ss0 += __shfl_xor_sync(0xffffffffu, ss0, o);
            ss1 += __shfl_xor_sync(0xffffffffu, ss1, o);
        }
        int pb = (k >> 1) & 1;
        if (lane == 0) { wred[pb][0][w] = ss0; wred[pb][1][w] = ss1; }
        __syncthreads();                   // ONE barrier per two rows
        float t0 = wred[pb][0][0] + wred[pb][0][1] + wred[pb][0][2] + wred[pb][0][3]
                 + wred[pb][0][4] + wred[pb][0][5] + wred[pb][0][6] + wred[pb][0][7];
        float t1 = wred[pb][1][0] + wred[pb][1][1] + wred[pb][1][2] + wred[pb][1][3]
                 + wred[pb][1][4] + wred[pb][1][5] + wred[pb][1][6] + wred[pb][1][7];
        float i0 = rsqrtf(fmaxf(t0, 1e-24f));
        float i1 = rsqrtf(fmaxf(t1, 1e-24f));
        a0 += x0.x * i0 + x1.x * i1; a1 += x0.y * i0 + x1.y * i1;
        a2 += x0.z * i0 + x1.z * i1; a3 += x0.w * i0 + x1.w * i1;
        a4 += y0.x * i0 + y1.x * i1; a5 += y0.y * i0 + y1.y * i1;
        a6 += y0.z * i0 + y1.z * i1; a7 += y0.w * i0 + y1.w * i1;
    }
    if (k < K) {                     // odd tail row
        cpa_wait<0>();
        int sb = k & (S_ - 1);
        float4 x = *(const float4*)&stg[sb][t * 4];
        float4 y = *(const float4*)&stg[sb][1024 + t * 4];
        float ss = warpSum(dot8(x, y));
        if (lane == 0) wred[0][0][w] = ss;
        __syncthreads();
        float tt = wred[0][0][0] + wred[0][0][1] + wred[0][0][2] + wred[0][0][3]
                 + wred[0][0][4] + wred[0][0][5] + wred[0][0][6] + wred[0][0][7];
        float iv = rsqrtf(fmaxf(tt, 1e-24f));
        a0 += x.x * iv; a1 += x.y * iv; a2 += x.z * iv; a3 += x.w * iv;
        a4 += y.x * iv; a5 += y.y * iv; a6 += y.z * iv; a7 += y.w * iv;
    }

    float ss2 = a0 * a0 + a1 * a1 + a2 * a2 + a3 * a3
              + a4 * a4 + a5 * a5 + a6 * a6 + a7 * a7;
    ss2 = warpSum(ss2);
    __syncthreads();
    if (lane == 0) wred[0][0][w] = ss2;
    __syncthreads();
    float tot2 = wred[0][0][0] + wred[0][0][1] + wred[0][0][2] + wred[0][0][3]
               + wred[0][0][4] + wred[0][0][5] + wred[0][0][6] + wred[0][0][7];
    float nrm  = sqrtf(tot2);
    float inv2 = 1.f / fmaxf(nrm, EPSF);

    __nv_bfloat16* cb = &g_cbf[m][c][0];
    uint2 u0, u1;
    u0.x = bfpack(a0 * inv2, a1 * inv2); u0.y = bfpack(a2 * inv2, a3 * inv2);
    u1.x = bfpack(a4 * inv2, a5 * inv2); u1.y = bfpack(a6 * inv2, a7 * inv2);
    *(uint2*)(cb + 4 * t)         = u0;
    *(uint2*)(cb + 4 * (t + 256)) = u1;
    if (t == 0) atomicAdd(&g_sumnorm, nrm);
}

// ---------------- kernel 2: split-K bf16 mma GEMM, 2-stage cp.async --------
// grid (8, 8, 12): z = p*4 + ks. Each block: 64x64 tile over K=512 (8 chunks).
#define KC_ 64
#define NC_ (512 / KC_)
__device__ __forceinline__ unsigned sw_off(int row, int g) {
    return (unsigned)(row * 128 + ((g ^ (row & 7)) << 4));
}

__global__ void __launch_bounds__(128) k2_gemm() {
    __shared__ __align__(16) unsigned char As[2][64 * 128];
    __shared__ __align__(16) unsigned char Bs[2][64 * 128];

    int z  = blockIdx.z;
    int p  = z >> 2, ks = z & 3;
    int pa = (p == 2) ? 1 : 0;
    int pb = (p == 0) ? 1 : 2;
    const __nv_bfloat16* A = &g_cbf[pa][0][0];
    const __nv_bfloat16* B = &g_cbf[pb][0][0];

    int t = threadIdx.x, lane = t & 31, warp = t >> 5;
    int wr = warp >> 1, wc = warp & 1;
    int brow = blockIdx.y * 64, bcol = blockIdx.x * 64;
    int k0 = ks * 512;

    float acc[2][4][4];
#pragma unroll
    for (int mt = 0; mt < 2; mt++)
#pragma unroll
        for (int nt = 0; nt < 4; nt++)
#pragma unroll
            for (int e = 0; e < 4; e++) acc[mt][nt][e] = 0.f;

    int rsel = lane & 15, gsel = lane >> 4;

#pragma unroll
    for (int j = 0; j < 4; j++) {
        int i = t + j * 128, row = i >> 3, g = i & 7;
        cpa16(&As[0][sw_off(row, g)], A + (size_t)(brow + row) * D_ + k0 + g * 8);
        cpa16(&Bs[0][sw_off(row, g)], B + (size_t)(bcol + row) * D_ + k0 + g * 8);
    }
    cpa_commit();

    for (int lc = 0; lc < NC_; lc++) {
        int st = lc & 1;
        if (lc + 1 < NC_) {
            int co = k0 + (lc + 1) * KC_;
            int ns = st ^ 1;
#pragma unroll
            for (int j = 0; j < 4; j++) {
                int i = t + j * 128, row = i >> 3, g = i & 7;
                cpa16(&As[ns][sw_off(row, g)], A + (size_t)(brow + row) * D_ + co + g * 8);
                cpa16(&Bs[ns][sw_off(row, g)], B + (size_t)(bcol + row) * D_ + co + g * 8);
            }
            cpa_commit();
            cpa_wait<1>();
        } else {
            cpa_wait<0>();
        }
        __syncthreads();

        unsigned ab = (unsigned)__cvta_generic_to_shared(&As[st][0]);
        unsigned bb = (unsigned)__cvta_generic_to_shared(&Bs[st][0]);
#pragma unroll
        for (int kh = 0; kh < 4; kh++) {
            unsigned af[2][4], bfr[2][4];
#pragma unroll
            for (int mt = 0; mt < 2; mt++) {
                unsigned ad = ab + sw_off(wr * 32 + mt * 16 + rsel, kh * 2 + gsel);
                asm volatile("ldmatrix.sync.aligned.m8n8.x4.shared.b16 {%0,%1,%2,%3}, [%4];"
                             : "=r"(af[mt][0]), "=r"(af[mt][1]), "=r"(af[mt][2]), "=r"(af[mt][3])
                             : "r"(ad));
            }
#pragma unroll
            for (int np = 0; np < 2; np++) {
                unsigned bd = bb + sw_off(wc * 32 + np * 16 + rsel, kh * 2 + gsel);
                asm volatile("ldmatrix.sync.aligned.m8n8.x4.shared.b16 {%0,%1,%2,%3}, [%4];"
                             : "=r"(bfr[np][0]), "=r"(bfr[np][1]), "=r"(bfr[np][2]), "=r"(bfr[np][3])
                             : "r"(bd));
            }
#pragma unroll
            for (int mt = 0; mt < 2; mt++)
#pragma unroll
                for (int nt = 0; nt < 4; nt++) {
                    int np = nt >> 1, s = nt & 1;
                    asm volatile(
                        "mma.sync.aligned.m16n8k16.row.col.f32.bf16.bf16.f32 "
                        "{%0,%1,%2,%3},{%4,%5,%6,%7},{%8,%9},{%0,%1,%2,%3};"
                        : "+f"(acc[mt][nt][0]), "+f"(acc[mt][nt][1]),
                          "+f"(acc[mt][nt][2]), "+f"(acc[mt][nt][3])
                        : "r"(af[mt][0]), "r"(af[mt][1]), "r"(af[mt][2]), "r"(af[mt][3]),
                          "r"(bfr[np][0 + s]), "r"(bfr[np][2 + s]));
                }
        }
        __syncthreads();
    }

    float* C = &g_part[p][ks][0][0];
#pragma unroll
    for (int mt = 0; mt < 2; mt++)
#pragma unroll
        for (int nt = 0; nt < 4; nt++) {
            int row = brow + wr * 32 + mt * 16 + (lane >> 2);
            int col = bcol + wc * 32 + nt * 8 + (lane & 3) * 2;
            *(float2*)(C + (size_t)row * P_ + col)       = make_float2(acc[mt][nt][0], acc[mt][nt][1]);
            *(float2*)(C + (size_t)(row + 8) * P_ + col) = make_float2(acc[mt][nt][2], acc[mt][nt][3]);
        }
}

// ---------------- kernel 3a: combine splits + exp-sum + diag, warp/row -----
// grid 192, block 256 (8 warps). Logits bounded (|2*dot|<=2): no max shift.
__global__ void __launch_bounds__(256) k3_row() {
    int warp = threadIdx.x >> 5, lane = threadIdx.x & 31;
    int gid = blockIdx.x * 8 + warp;          // 0 .. 1535
    int p = gid >> 9, i = gid & (P_ - 1);
    const float* b0 = &g_part[p][0][i][0];    // plane stride P_*P_

    float es = 0.f, dg = 0.f;
#pragma unroll
    for (int j = 0; j < 4; j++) {
        int c0 = lane * 4 + j * 128;
        float4 v0 = *(const float4*)(b0 + c0);
        float4 v1 = *(const float4*)(b0 + P_ * P_ + c0);
        float4 v2 = *(const float4*)(b0 + 2 * P_ * P_ + c0);
        float4 v3 = *(const float4*)(b0 + 3 * P_ * P_ + c0);
        float sx = v0.x + v1.x + v2.x + v3.x;
        float sy = v0.y + v1.y + v2.y + v3.y;
        float sz = v0.z + v1.z + v2.z + v3.z;
        float sw = v0.w + v1.w + v2.w + v3.w;
        es += __expf(2.f * sx) + __expf(2.f * sy)
            + __expf(2.f * sz) + __expf(2.f * sw);
        if (i == c0)     dg += sx;
        if (i == c0 + 1) dg += sy;
        if (i == c0 + 2) dg += sz;
        if (i == c0 + 3) dg += sw;
    }
    es = warpSum(es);
    dg = warpSum(dg);
    if (lane == 0) g_rowloss[gid] = __logf(es) - 2.f * dg;
}

// ---------------- kernel 3b: final scalar ----------------------------------
__global__ void __launch_bounds__(512) k3_final(float* __restrict__ out) {
    int t = threadIdx.x;  // 512 threads
    float rl = g_rowloss[t] + g_rowloss[t + 512] + g_rowloss[t + 1024];
    __shared__ float w1[16];
    rl = warpSum(rl);
    if ((t & 31) == 0) w1[t >> 5] = rl;
    __syncthreads();
    if (t == 0) {
        float R = 0.f;
        for (int i = 0; i < 16; i++) R += w1[i];
        // loss_intra = 6 - (2/N)*sum||s||;  loss_inter = (sum rowloss)/P
        out[0] = 6.f - g_sumnorm / 4096.f + R / 512.f;
    }
}

// ---------------- launch: serial single stream (proven R13 order) ----------
extern "C" void kernel_launch(void* const* d_in, const int* in_sizes, int n_in,
                              void* d_out, int out_size) {
    const float* fv    = (const float*)d_in[0];
    const float* fa    = (const float*)d_in[1];
    const float* fr    = (const float*)d_in[2];
    const int*   label = (const int*)d_in[3];
    (void)in_sizes; (void)n_in; (void)out_size;

    k0a_hist<<<NB_, 512>>>(label);
    k0b_fill<<<NB_, 512>>>(label);
    k1_centers<<<dim3(P_, 3), 256>>>(fv, fa, fr);
    k2_gemm<<<dim3(8, 8, 12), 128>>>();
    k3_row<<<192, 256>>>();
    k3_final<<<1, 512>>>((float*)d_out);
}

// round 16
// speedup vs baseline: 1.3061x; 1.0385x over previous
#include <cuda_runtime.h>
#include <cuda_bf16.h>
#include <math.h>

#define N_   8192
#define D_   2048
#define P_   512
#define NB_  16          // k0 partition blocks (512 samples each)
#define EPSF 1e-12f
#define S_   4           // k1 LDGSTS ring depth (4 x 8KB static smem)

// ---------------- scratch (device globals; no allocation allowed) ----------
__device__ int   g_count[P_];
__device__ int   g_offset[P_];
__device__ int   g_members[N_];
__device__ __nv_bfloat16 g_cbf[3][P_][D_];   // unit centers, bf16
__device__ float g_part[3][4][P_][P_];       // split-K partial dot planes (12MB)
__device__ float g_sumnorm;                  // sum ||s_c|| over all (m, c)
__device__ float g_rlsum;                    // sum of row losses
__device__ unsigned g_done;                  // k3 completion counter

// ---------------- helpers --------------------------------------------------
__device__ __forceinline__ float warpSum(float v) {
#pragma unroll
    for (int o = 16; o; o >>= 1) v += __shfl_xor_sync(0xffffffffu, v, o);
    return v;
}
__device__ __forceinline__ unsigned bfpack(float lo, float hi) {
    unsigned a = (unsigned)__bfloat16_as_ushort(__float2bfloat16_rn(lo));
    unsigned b = (unsigned)__bfloat16_as_ushort(__float2bfloat16_rn(hi));
    return a | (b << 16);
}
__device__ __forceinline__ float dot8(const float4& x, const float4& y) {
    return x.x * x.x + x.y * x.y + x.z * x.z + x.w * x.w
         + y.x * y.x + y.y * y.y + y.z * y.z + y.w * y.w;
}
__device__ __forceinline__ void cpa16(void* dst, const void* src) {
    unsigned d = (unsigned)__cvta_generic_to_shared(dst);
    asm volatile("cp.async.cg.shared.global [%0], [%1], 16;\n" :: "r"(d), "l"(src));
}
__device__ __forceinline__ void cpa_commit() {
    asm volatile("cp.async.commit_group;\n" ::: "memory");
}
template <int Npend>
__device__ __forceinline__ void cpa_wait() {
    asm volatile("cp.async.wait_group %0;\n" :: "n"(Npend) : "memory");
}

// ---------------- kernel 0: member list build, ONE launch (grid NB_) -------
// Each block histograms ALL labels (L2-resident, 32KB) while counting its
// own before-prefix, shfl-scans, then fills its own 512-sample partition.
__global__ void __launch_bounds__(512) k0_all(const int* __restrict__ label) {
    __shared__ int tot[P_], bef[P_];
    __shared__ int ws[16];
    int t = threadIdx.x, b = blockIdx.x, lane = t & 31, w = t >> 5;

    tot[t] = 0; bef[t] = 0;
    __syncthreads();
    int myl = 0;
#pragma unroll
    for (int j = 0; j < NB_; j++) {
        int l = __ldg(&label[j * 512 + t]);
        if (j == b) myl = l;
        atomicAdd(&tot[l], 1);
        if (j < b) atomicAdd(&bef[l], 1);
    }
    __syncthreads();

    int mytot = tot[t];
    int inc = mytot;
#pragma unroll
    for (int o = 1; o < 32; o <<= 1) {
        int v = __shfl_up_sync(0xffffffffu, inc, o);
        if (lane >= o) inc += v;
    }
    if (lane == 31) ws[w] = inc;
    __syncthreads();
    if (t < 32) {
        int v = (t < 16) ? ws[t] : 0;
        int s = v;
#pragma unroll
        for (int o = 1; o < 32; o <<= 1) {
            int u = __shfl_up_sync(0xffffffffu, s, o);
            if (lane >= o) s += u;
        }
        if (t < 16) ws[t] = s - v;
    }
    __syncthreads();
    int exc = ws[w] + inc - mytot;        // exclusive class prefix
    if (b == 0) {
        g_count[t]  = mytot;
        g_offset[t] = exc;
        if (t == 0) { g_sumnorm = 0.f; g_rlsum = 0.f; g_done = 0u; }
    }
    bef[t] = exc + bef[t];                // this partition's write cursor
    __syncthreads();
    int pos = atomicAdd(&bef[myl], 1);
    g_members[pos] = b * 512 + t;
}

// ---------------- kernel 1: centers, LDGSTS ring + row pairing -------------
// grid (P_, 3), block 256. 4-stage ring; two rows per barrier (ILP'd shfl
// chains, half the barriers).
__global__ void __launch_bounds__(256) k1_centers(const float* __restrict__ f0,
                                                  const float* __restrict__ f1,
                                                  const float* __restrict__ f2) {
    int c = blockIdx.x, m = blockIdx.y;
    const float* f = (m == 0) ? f0 : ((m == 1) ? f1 : f2);
    int off = g_offset[c];
    int K   = g_count[c];
    int t   = threadIdx.x, w = t >> 5, lane = t & 31;

    __shared__ __align__(16) float stg[S_][D_];   // 32 KB ring
    __shared__ float wred[2][2][8];               // [pair parity][row][warp]

#pragma unroll
    for (int s = 0; s < S_; s++) {
        if (s < K) {
            int row = __ldg(&g_members[off + s]);
            const float* src = f + (size_t)row * D_;
            cpa16(&stg[s][t * 4], src + t * 4);
            cpa16(&stg[s][1024 + t * 4], src + 1024 + t * 4);
        }
        cpa_commit();
    }

    float a0 = 0.f, a1 = 0.f, a2 = 0.f, a3 = 0.f;
    float a4 = 0.f, a5 = 0.f, a6 = 0.f, a7 = 0.f;

    int k = 0;
    for (; k + 1 < K; k += 2) {
        cpa_wait<S_ - 2>();          // stages k and k+1 landed
        int sb0 = k & (S_ - 1), sb1 = (k + 1) & (S_ - 1);
        float4 x0 = *(const float4*)&stg[sb0][t * 4];
        float4 y0 = *(const float4*)&stg[sb0][1024 + t * 4];
        float4 x1 = *(const float4*)&stg[sb1][t * 4];
        float4 y1 = *(const float4*)&stg[sb1][1024 + t * 4];
        int kn0 = k + S_, kn1 = k + 1 + S_;
        if (kn0 < K) {
            int row = __ldg(&g_members[off + kn0]);
            const float* src = f + (size_t)row * D_;
            cpa16(&stg[sb0][t * 4], src + t * 4);
            cpa16(&stg[sb0][1024 + t * 4], src + 1024 + t * 4);
        }
        cpa_commit();
        if (kn1 < K) {
            int row = __ldg(&g_members[off + kn1]);
            const float* src = f + (size_t)row * D_;
            cpa16(&stg[sb1][t * 4], src + t * 4);
            cpa16(&stg[sb1][1024 + t * 4], src + 1024 + t * 4);
        }
        cpa_commit();

        float ss0 = dot8(x0, y0), ss1 = dot8(x1, y1);
#pragma unroll
        for (int o = 16; o; o >>= 1) {     // two interleaved shfl chains (ILP)
            ss0 += __shfl_xor_sync(0xffffffffu, ss0, o);
            ss1 += __shfl_xor_sync(0xffffffffu, ss1, o);
        }
        int pb = (k >> 1) & 1;
        if (lane == 0) { wred[pb][0][w] = ss0; wred[pb][1][w] = ss1; }
        __syncthreads();                   // ONE barrier per two rows
        float t0 = wred[pb][0][0] + wred[pb][0][1] + wred[pb][0][2] + wred[pb][0][3]
                 + wred[pb][0][4] + wred[pb][0][5] + wred[pb][0][6] + wred[pb][0][7];
        float t1 = wred[pb][1][0] + wred[pb][1][1] + wred[pb][1][2] + wred[pb][1][3]
                 + wred[pb][1][4] + wred[pb][1][5] + wred[pb][1][6] + wred[pb][1][7];
        float i0 = rsqrtf(fmaxf(t0, 1e-24f));
        float i1 = rsqrtf(fmaxf(t1, 1e-24f));
        a0 += x0.x * i0 + x1.x * i1; a1 += x0.y * i0 + x1.y * i1;
        a2 += x0.z * i0 + x1.z * i1; a3 += x0.w * i0 + x1.w * i1;
        a4 += y0.x * i0 + y1.x * i1; a5 += y0.y * i0 + y1.y * i1;
        a6 += y0.z * i0 + y1.z * i1; a7 += y0.w * i0 + y1.w * i1;
    }
    if (k < K) {                     // odd tail row
        cpa_wait<0>();
        int sb = k & (S_ - 1);
        float4 x = *(const float4*)&stg[sb][t * 4];
        float4 y = *(const float4*)&stg[sb][1024 + t * 4];
        float ss = warpSum(dot8(x, y));
        if (lane == 0) wred[0][0][w] = ss;
        __syncthreads();
        float tt = wred[0][0][0] + wred[0][0][1] + wred[0][0][2] + wred[0][0][3]
                 + wred[0][0][4] + wred[0][0][5] + wred[0][0][6] + wred[0][0][7];
        float iv = rsqrtf(fmaxf(tt, 1e-24f));
        a0 += x.x * iv; a1 += x.y * iv; a2 += x.z * iv; a3 += x.w * iv;
        a4 += y.x * iv; a5 += y.y * iv; a6 += y.z * iv; a7 += y.w * iv;
    }

    float ss2 = a0 * a0 + a1 * a1 + a2 * a2 + a3 * a3
              + a4 * a4 + a5 * a5 + a6 * a6 + a7 * a7;
    ss2 = warpSum(ss2);
    __syncthreads();
    if (lane == 0) wred[0][0][w] = ss2;
    __syncthreads();
    float tot2 = wred[0][0][0] + wred[0][0][1] + wred[0][0][2] + wred[0][0][3]
               + wred[0][0][4] + wred[0][0][5] + wred[0][0][6] + wred[0][0][7];
    float nrm  = sqrtf(tot2);
    float inv2 = 1.f / fmaxf(nrm, EPSF);

    __nv_bfloat16* cb = &g_cbf[m][c][0];
    uint2 u0, u1;
    u0.x = bfpack(a0 * inv2, a1 * inv2); u0.y = bfpack(a2 * inv2, a3 * inv2);
    u1.x = bfpack(a4 * inv2, a5 * inv2); u1.y = bfpack(a6 * inv2, a7 * inv2);
    *(uint2*)(cb + 4 * t)         = u0;
    *(uint2*)(cb + 4 * (t + 256)) = u1;
    if (t == 0) atomicAdd(&g_sumnorm, nrm);
}

// ---------------- kernel 2: split-K bf16 mma GEMM, 3-stage cp.async --------
// grid (8, 8, 12): z = p*4 + ks. 64x64 tile over K=512 (8 chunks of 64).
// 3-stage ring, ONE barrier per chunk: wait<1> -> sync -> issue chunk lc+2
// into the stage freed at the sync -> mma on chunk lc. Two chunks in flight.
#define KC_ 64
#define NC_ (512 / KC_)
__device__ __forceinline__ unsigned sw_off(int row, int g) {
    return (unsigned)(row * 128 + ((g ^ (row & 7)) << 4));
}

__global__ void __launch_bounds__(128) k2_gemm() {
    __shared__ __align__(16) unsigned char As[3][64 * 128];
    __shared__ __align__(16) unsigned char Bs[3][64 * 128];

    int z  = blockIdx.z;
    int p  = z >> 2, ks = z & 3;
    int pa = (p == 2) ? 1 : 0;
    int pb = (p == 0) ? 1 : 2;
    const __nv_bfloat16* A = &g_cbf[pa][0][0];
    const __nv_bfloat16* B = &g_cbf[pb][0][0];

    int t = threadIdx.x, lane = t & 31, warp = t >> 5;
    int wr = warp >> 1, wc = warp & 1;
    int brow = blockIdx.y * 64, bcol = blockIdx.x * 64;
    int k0 = ks * 512;

    float acc[2][4][4];
#pragma unroll
    for (int mt = 0; mt < 2; mt++)
#pragma unroll
        for (int nt = 0; nt < 4; nt++)
#pragma unroll
            for (int e = 0; e < 4; e++) acc[mt][nt][e] = 0.f;

    int rsel = lane & 15, gsel = lane >> 4;

    // prologue: chunks 0 and 1 into stages 0 and 1
#pragma unroll
    for (int s = 0; s < 2; s++) {
        int co = k0 + s * KC_;
#pragma unroll
        for (int j = 0; j < 4; j++) {
            int i = t + j * 128, row = i >> 3, g = i & 7;
            cpa16(&As[s][sw_off(row, g)], A + (size_t)(brow + row) * D_ + co + g * 8);
            cpa16(&Bs[s][sw_off(row, g)], B + (size_t)(bcol + row) * D_ + co + g * 8);
        }
        cpa_commit();
    }

    for (int lc = 0; lc < NC_; lc++) {
        cpa_wait<1>();             // chunk lc landed (lc+1 may still fly)
        __syncthreads();           // prev iter's reads of stage (lc+2)%3 done

        if (lc + 2 < NC_) {        // refill the just-freed stage
            int ns = (lc + 2) % 3;
            int co = k0 + (lc + 2) * KC_;
#pragma unroll
            for (int j = 0; j < 4; j++) {
                int i = t + j * 128, row = i >> 3, g = i & 7;
                cpa16(&As[ns][sw_off(row, g)], A + (size_t)(brow + row) * D_ + co + g * 8);
                cpa16(&Bs[ns][sw_off(row, g)], B + (size_t)(bcol + row) * D_ + co + g * 8);
            }
        }
        cpa_commit();              // real or empty: keeps wait<1> exact

        int st = lc % 3;
        unsigned ab = (unsigned)__cvta_generic_to_shared(&As[st][0]);
        unsigned bb = (unsigned)__cvta_generic_to_shared(&Bs[st][0]);
#pragma unroll
        for (int kh = 0; kh < 4; kh++) {
            unsigned af[2][4], bfr[2][4];
#pragma unroll
            for (int mt = 0; mt < 2; mt++) {
                unsigned ad = ab + sw_off(wr * 32 + mt * 16 + rsel, kh * 2 + gsel);
                asm volatile("ldmatrix.sync.aligned.m8n8.x4.shared.b16 {%0,%1,%2,%3}, [%4];"
                             : "=r"(af[mt][0]), "=r"(af[mt][1]), "=r"(af[mt][2]), "=r"(af[mt][3])
                             : "r"(ad));
            }
#pragma unroll
            for (int np = 0; np < 2; np++) {
                unsigned bd = bb + sw_off(wc * 32 + np * 16 + rsel, kh * 2 + gsel);
                asm volatile("ldmatrix.sync.aligned.m8n8.x4.shared.b16 {%0,%1,%2,%3}, [%4];"
                             : "=r"(bfr[np][0]), "=r"(bfr[np][1]), "=r"(bfr[np][2]), "=r"(bfr[np][3])
                             : "r"(bd));
            }
#pragma unroll
            for (int mt = 0; mt < 2; mt++)
#pragma unroll
                for (int nt = 0; nt < 4; nt++) {
                    int np = nt >> 1, s = nt & 1;
                    asm volatile(
                        "mma.sync.aligned.m16n8k16.row.col.f32.bf16.bf16.f32 "
                        "{%0,%1,%2,%3},{%4,%5,%6,%7},{%8,%9},{%0,%1,%2,%3};"
                        : "+f"(acc[mt][nt][0]), "+f"(acc[mt][nt][1]),
                          "+f"(acc[mt][nt][2]), "+f"(acc[mt][nt][3])
                        : "r"(af[mt][0]), "r"(af[mt][1]), "r"(af[mt][2]), "r"(af[mt][3]),
                          "r"(bfr[np][0 + s]), "r"(bfr[np][2 + s]));
                }
        }
    }

    float* C = &g_part[p][ks][0][0];
#pragma unroll
    for (int mt = 0; mt < 2; mt++)
#pragma unroll
        for (int nt = 0; nt < 4; nt++) {
            int row = brow + wr * 32 + mt * 16 + (lane >> 2);
            int col = bcol + wc * 32 + nt * 8 + (lane & 3) * 2;
            *(float2*)(C + (size_t)row * P_ + col)       = make_float2(acc[mt][nt][0], acc[mt][nt][1]);
            *(float2*)(C + (size_t)(row + 8) * P_ + col) = make_float2(acc[mt][nt][2], acc[mt][nt][3]);
        }
}

// ---------------- kernel 3: combine splits + exp-sum + diag + FINAL --------
// grid 192, block 256 (8 warps, warp-per-row). Logits bounded: no max shift.
// Block-reduces row losses, atomicAdds once per block, last block writes out.
__global__ void __launch_bounds__(256) k3_row(float* __restrict__ out) {
    int warp = threadIdx.x >> 5, lane = threadIdx.x & 31;
    int gid = blockIdx.x * 8 + warp;          // 0 .. 1535
    int p = gid >> 9, i = gid & (P_ - 1);
    const float* b0 = &g_part[p][0][i][0];    // plane stride P_*P_

    float es = 0.f, dg = 0.f;
#pragma unroll
    for (int j = 0; j < 4; j++) {
        int c0 = lane * 4 + j * 128;
        float4 v0 = *(const float4*)(b0 + c0);
        float4 v1 = *(const float4*)(b0 + P_ * P_ + c0);
        float4 v2 = *(const float4*)(b0 + 2 * P_ * P_ + c0);
        float4 v3 = *(const float4*)(b0 + 3 * P_ * P_ + c0);
        float sx = v0.x + v1.x + v2.x + v3.x;
        float sy = v0.y + v1.y + v2.y + v3.y;
        float sz = v0.z + v1.z + v2.z + v3.z;
        float sw = v0.w + v1.w + v2.w + v3.w;
        es += __expf(2.f * sx) + __expf(2.f * sy)
            + __expf(2.f * sz) + __expf(2.f * sw);
        if (i == c0)     dg += sx;
        if (i == c0 + 1) dg += sy;
        if (i == c0 + 2) dg += sz;
        if (i == c0 + 3) dg += sw;
    }
    es = warpSum(es);
    dg = warpSum(dg);

    __shared__ float wloss[8];
    if (lane == 0) wloss[warp] = __logf(es) - 2.f * dg;
    __syncthreads();
    if (threadIdx.x == 0) {
        float bsum = wloss[0] + wloss[1] + wloss[2] + wloss[3]
                   + wloss[4] + wloss[5] + wloss[6] + wloss[7];
        atomicAdd(&g_rlsum, bsum);
        __threadfence();
        unsigned old = atomicAdd(&g_done, 1u);
        if (old == 191u) {                    // last block assembles the loss
            __threadfence();
            float R = atomicAdd(&g_rlsum, 0.f);
            out[0] = 6.f - g_sumnorm / 4096.f + R / 512.f;
        }
    }
}

// ---------------- launch: serial single stream -----------------------------
extern "C" void kernel_launch(void* const* d_in, const int* in_sizes, int n_in,
                              void* d_out, int out_size) {
    const float* fv    = (const float*)d_in[0];
    const float* fa    = (const float*)d_in[1];
    const float* fr    = (const float*)d_in[2];
    const int*   label = (const int*)d_in[3];
    (void)in_sizes; (void)n_in; (void)out_size;

    k0_all<<<NB_, 512>>>(label);
    k1_centers<<<dim3(P_, 3), 256>>>(fv, fa, fr);
    k2_gemm<<<dim3(8, 8, 12), 128>>>();
    k3_row<<<192, 256>>>((float*)d_out);
}